// round 1
// baseline (speedup 1.0000x reference)
#include <cuda_runtime.h>

#define BATCH 8
#define NN    4096
#define DD    64
#define EPS_F 1e-8f

// Scratch (no allocations allowed): G = dinv * (X@W + b)  [B,N,D], dinv [B,N]
__device__ float g_G[BATCH * NN * DD];
__device__ float g_dinv[BATCH * NN];

// ---------------- f32x2 packed helpers (Blackwell) ----------------
__device__ __forceinline__ unsigned long long splat2(float x) {
    unsigned long long r;
    asm("mov.b64 %0, {%1, %1};" : "=l"(r) : "f"(x));
    return r;
}
__device__ __forceinline__ void fma2(unsigned long long& d,
                                     unsigned long long a,
                                     unsigned long long b) {
    asm("fma.rn.f32x2 %0, %1, %2, %3;" : "=l"(d) : "l"(a), "l"(b), "l"(d));
}
__device__ __forceinline__ float2 unpack2(unsigned long long v) {
    float2 r;
    asm("mov.b64 {%0, %1}, %2;" : "=f"(r.x), "=f"(r.y) : "l"(v));
    return r;
}

// ---------------- Kernel 1: degree + linear layer, fused ----------------
// One warp per (b, row): dinv = rsqrt(max(rowsum(A)+1, eps));
// G[row] = dinv * (X[row] @ W + b); also store dinv.
__global__ __launch_bounds__(256) void k_prep(
    const float* __restrict__ X, const float* __restrict__ A,
    const float* __restrict__ W, const float* __restrict__ bias)
{
    __shared__ float Ws[DD * DD];
    for (int i = threadIdx.x; i < DD * DD; i += 256) Ws[i] = W[i];
    __syncthreads();

    int wg   = blockIdx.x * 8 + (threadIdx.x >> 5);   // global warp = b*NN + row
    int lane = threadIdx.x & 31;

    // Row sum of A (vectorized, coalesced)
    const float4* A4 = (const float4*)(A + (size_t)wg * NN);
    float s = 0.f;
    #pragma unroll 8
    for (int i = lane; i < NN / 4; i += 32) {
        float4 v = A4[i];
        s += (v.x + v.y) + (v.z + v.w);
    }
    #pragma unroll
    for (int o = 16; o; o >>= 1) s += __shfl_xor_sync(0xffffffffu, s, o);
    float dinv = rsqrtf(fmaxf(s + 1.0f, EPS_F));
    if (lane == 0) g_dinv[wg] = dinv;

    // H row: each lane computes output cols (2*lane, 2*lane+1)
    const float* Xrow = X + (size_t)wg * DD;
    const float2* W2  = (const float2*)Ws;
    float2 bv = ((const float2*)bias)[lane];
    float h0 = bv.x, h1 = bv.y;
    #pragma unroll
    for (int k = 0; k < DD; ++k) {
        float  x = Xrow[k];
        float2 w = W2[k * 32 + lane];
        h0 = fmaf(x, w.x, h0);
        h1 = fmaf(x, w.y, h1);
    }
    float2 g;
    g.x = dinv * h0;
    g.y = dinv * h1;
    ((float2*)(g_G + (size_t)wg * DD))[lane] = g;
}

// ---------------- Kernel 2: out = dinv_i * (A @ G + G_i) ----------------
// CTA tile: 64 rows x 64 cols, K = 4096 streamed in KT=16 chunks,
// double-buffered smem. G is stored in smem pre-splatted as f32x2 so the
// inner loop is pure LDS.128 + fma.rn.f32x2 (no pack instructions).
#define KT 16
#define MT 64

__global__ __launch_bounds__(256) void k_agg(
    const float* __restrict__ A, float* __restrict__ out)
{
    __shared__ __align__(16) float              As[2][KT][MT + 4];  // k-major, padded
    __shared__ __align__(16) unsigned long long Gs[2][KT][DD];      // splatted (g,g)

    int b    = blockIdx.y;
    int row0 = blockIdx.x * MT;
    const float* Ab = A   + ((size_t)b * NN + row0) * NN;
    const float* Gb = g_G + (size_t)b * NN * DD;

    int t  = threadIdx.x;
    int tx = t & 15;        // col group: cols 4*tx .. 4*tx+3
    int ty = t >> 4;        // row group: rows 4*ty .. 4*ty+3

    // Load assignments (one float4 of A + one float4 of G per thread per tile)
    int a_row = t >> 2;          // 0..63
    int a_kg  = (t & 3) * 4;     // 0,4,8,12
    int gl_k  = t >> 4;          // 0..15
    int gl_c  = (t & 15) * 4;    // 0..60
    const float* Aptr = Ab + (size_t)a_row * NN + a_kg;
    const float* Gptr = Gb + gl_k * DD + gl_c;

    unsigned long long acc[2][4];
    #pragma unroll
    for (int i = 0; i < 2; ++i)
        #pragma unroll
        for (int j = 0; j < 4; ++j) acc[i][j] = 0ull;

    // Prologue: stage tile 0
    float4 av = *(const float4*)(Aptr);
    float4 gv = *(const float4*)(Gptr);
    As[0][a_kg + 0][a_row] = av.x;
    As[0][a_kg + 1][a_row] = av.y;
    As[0][a_kg + 2][a_row] = av.z;
    As[0][a_kg + 3][a_row] = av.w;
    Gs[0][gl_k][gl_c + 0] = splat2(gv.x);
    Gs[0][gl_k][gl_c + 1] = splat2(gv.y);
    Gs[0][gl_k][gl_c + 2] = splat2(gv.z);
    Gs[0][gl_k][gl_c + 3] = splat2(gv.w);
    __syncthreads();

    const int NTILE = NN / KT;   // 256
    for (int kt = 0; kt < NTILE; ++kt) {
        int cur = kt & 1;
        if (kt + 1 < NTILE) {
            av = *(const float4*)(Aptr + (size_t)(kt + 1) * KT);
            gv = *(const float4*)(Gptr + (size_t)(kt + 1) * KT * DD);
        }
        #pragma unroll
        for (int k = 0; k < KT; ++k) {
            // 4 rows of A as two f32x2 pairs straight from LDS.128
            ulonglong2 a01 = *(const ulonglong2*)&As[cur][k][4 * ty];
            ulonglong2 g01 = *(const ulonglong2*)&Gs[cur][k][4 * tx];
            ulonglong2 g23 = *(const ulonglong2*)&Gs[cur][k][4 * tx + 2];
            fma2(acc[0][0], a01.x, g01.x);
            fma2(acc[0][1], a01.x, g01.y);
            fma2(acc[0][2], a01.x, g23.x);
            fma2(acc[0][3], a01.x, g23.y);
            fma2(acc[1][0], a01.y, g01.x);
            fma2(acc[1][1], a01.y, g01.y);
            fma2(acc[1][2], a01.y, g23.x);
            fma2(acc[1][3], a01.y, g23.y);
        }
        if (kt + 1 < NTILE) {
            int nxt = cur ^ 1;
            As[nxt][a_kg + 0][a_row] = av.x;
            As[nxt][a_kg + 1][a_row] = av.y;
            As[nxt][a_kg + 2][a_row] = av.z;
            As[nxt][a_kg + 3][a_row] = av.w;
            Gs[nxt][gl_k][gl_c + 0] = splat2(gv.x);
            Gs[nxt][gl_k][gl_c + 1] = splat2(gv.y);
            Gs[nxt][gl_k][gl_c + 2] = splat2(gv.z);
            Gs[nxt][gl_k][gl_c + 3] = splat2(gv.w);
        }
        __syncthreads();
    }

    // Epilogue: out[i] = dinv_i * (acc_i + G_i)   (G_i is the A+I identity term)
    const float* dinvB = g_dinv + b * NN + row0;
    const float* Grow  = Gb + (size_t)row0 * DD;
    float*       outB  = out + ((size_t)b * NN + row0) * DD;
    #pragma unroll
    for (int rp = 0; rp < 2; ++rp) {
        float2 v0 = unpack2(acc[rp][0]);
        float2 v1 = unpack2(acc[rp][1]);
        float2 v2 = unpack2(acc[rp][2]);
        float2 v3 = unpack2(acc[rp][3]);
        #pragma unroll
        for (int h = 0; h < 2; ++h) {
            int   r  = 4 * ty + 2 * rp + h;
            float dv = dinvB[r];
            float4 gs = *(const float4*)(Grow + (size_t)r * DD + 4 * tx);
            float a0 = h ? v0.y : v0.x;
            float a1 = h ? v1.y : v1.x;
            float a2 = h ? v2.y : v2.x;
            float a3 = h ? v3.y : v3.x;
            float4 o;
            o.x = dv * (a0 + gs.x);
            o.y = dv * (a1 + gs.y);
            o.z = dv * (a2 + gs.z);
            o.w = dv * (a3 + gs.w);
            *(float4*)(outB + (size_t)r * DD + 4 * tx) = o;
        }
    }
}

// ---------------- launch ----------------
extern "C" void kernel_launch(void* const* d_in, const int* in_sizes, int n_in,
                              void* d_out, int out_size) {
    (void)in_sizes; (void)n_in; (void)out_size;
    const float* X    = (const float*)d_in[0];
    const float* A    = (const float*)d_in[1];
    const float* W    = (const float*)d_in[2];
    const float* bias = (const float*)d_in[3];
    float* out = (float*)d_out;

    k_prep<<<BATCH * NN / 8, 256>>>(X, A, W, bias);
    dim3 g2(NN / MT, BATCH);
    k_agg<<<g2, 256>>>(A, out);
}

// round 2
// speedup vs baseline: 2.2448x; 2.2448x over previous
#include <cuda_runtime.h>

#define BATCH 8
#define NN    4096
#define DD    64
#define EPS_F 1e-8f

// Scratch: G = dinv * (X@W + b)  [B,N,D], dinv [B,N]
__device__ float g_G[BATCH * NN * DD];
__device__ float g_dinv[BATCH * NN];

// ---------------- f32x2 packed helpers (Blackwell) ----------------
__device__ __forceinline__ unsigned long long splat2(float x) {
    unsigned long long r;
    asm("mov.b64 %0, {%1, %1};" : "=l"(r) : "f"(x));
    return r;
}
__device__ __forceinline__ void fma2(unsigned long long& d,
                                     unsigned long long a,
                                     unsigned long long b) {
    asm("fma.rn.f32x2 %0, %1, %2, %3;" : "=l"(d) : "l"(a), "l"(b), "l"(d));
}
__device__ __forceinline__ float2 unpack2(unsigned long long v) {
    float2 r;
    asm("mov.b64 {%0, %1}, %2;" : "=f"(r.x), "=f"(r.y) : "l"(v));
    return r;
}

// ---------------- Kernel 1: degree + linear layer, fused ----------------
__global__ __launch_bounds__(256) void k_prep(
    const float* __restrict__ X, const float* __restrict__ A,
    const float* __restrict__ W, const float* __restrict__ bias)
{
    __shared__ float Ws[DD * DD];
    for (int i = threadIdx.x; i < DD * DD; i += 256) Ws[i] = W[i];
    __syncthreads();

    int wg   = blockIdx.x * 8 + (threadIdx.x >> 5);   // global warp = b*NN + row
    int lane = threadIdx.x & 31;

    const float4* A4 = (const float4*)(A + (size_t)wg * NN);
    float s = 0.f;
    #pragma unroll 8
    for (int i = lane; i < NN / 4; i += 32) {
        float4 v = A4[i];
        s += (v.x + v.y) + (v.z + v.w);
    }
    #pragma unroll
    for (int o = 16; o; o >>= 1) s += __shfl_xor_sync(0xffffffffu, s, o);
    float dinv = rsqrtf(fmaxf(s + 1.0f, EPS_F));
    if (lane == 0) g_dinv[wg] = dinv;

    const float* Xrow = X + (size_t)wg * DD;
    const float2* W2  = (const float2*)Ws;
    float2 bv = ((const float2*)bias)[lane];
    float h0 = bv.x, h1 = bv.y;
    #pragma unroll
    for (int k = 0; k < DD; ++k) {
        float  x = Xrow[k];
        float2 w = W2[k * 32 + lane];
        h0 = fmaf(x, w.x, h0);
        h1 = fmaf(x, w.y, h1);
    }
    float2 g;
    g.x = dinv * h0;
    g.y = dinv * h1;
    ((float2*)(g_G + (size_t)wg * DD))[lane] = g;
}

// ---------------- Kernel 2: out = dinv_i * (A @ G + G_i) ----------------
// CTA: 128 rows x 64 cols, 128 threads, thread computes 8x8 outputs.
// A in smem plain fp32 k-major (row-pairs read as ulonglong2).
// G in smem splatted f32x2 per column, 16B-chunk XOR-swizzled.
#define KT 16
#define MT 128

// swizzled ull index for (k, col) in a [KT][64]-ull buffer
__device__ __forceinline__ int gswz(int c) {
    int chunk = c >> 1;                      // 16B chunk id (0..31)
    chunk ^= (chunk >> 3) & 3;               // spread across 128B bank spans
    return chunk * 2 + (c & 1);
}

__global__ __launch_bounds__(128) void k_agg(
    const float* __restrict__ A, float* __restrict__ out)
{
    __shared__ __align__(16) float              As[2][KT][MT + 4];
    __shared__ __align__(16) unsigned long long Gs[2][KT][DD];

    const int b    = blockIdx.y;
    const int row0 = blockIdx.x * MT;
    const float* Ab = A   + ((size_t)b * NN + row0) * NN;
    const float* Gb = g_G + (size_t)b * NN * DD;

    const int t  = threadIdx.x;
    const int tx = t & 7;      // col block: cols 8*tx .. 8*tx+7
    const int ty = t >> 3;     // row block: rows 8*ty .. 8*ty+7

    // A loader: kc = k-chunk (4 floats), row_l + 32*i rows
    const int a_kc  = t & 3;
    const int a_row = t >> 2;          // 0..31
    // G loader: fixed col, 8 k's
    const int g_c  = t & 63;
    const int g_k0 = t >> 6;           // 0..1
    const int g_sidx = gswz(g_c);

    unsigned long long acc[4][8];
    #pragma unroll
    for (int i = 0; i < 4; ++i)
        #pragma unroll
        for (int j = 0; j < 8; ++j) acc[i][j] = 0ull;

    float4 areg[4];
    float  greg[8];

    // ---- prologue: load tile 0 ----
    #pragma unroll
    for (int i = 0; i < 4; ++i)
        areg[i] = *(const float4*)(Ab + (size_t)(a_row + 32 * i) * NN + a_kc * 4);
    #pragma unroll
    for (int i = 0; i < 8; ++i)
        greg[i] = Gb[(size_t)(g_k0 + 2 * i) * DD + g_c];

    #pragma unroll
    for (int i = 0; i < 4; ++i) {
        int r = a_row + 32 * i;
        As[0][4 * a_kc + 0][r] = areg[i].x;
        As[0][4 * a_kc + 1][r] = areg[i].y;
        As[0][4 * a_kc + 2][r] = areg[i].z;
        As[0][4 * a_kc + 3][r] = areg[i].w;
    }
    #pragma unroll
    for (int i = 0; i < 8; ++i)
        Gs[0][g_k0 + 2 * i][g_sidx] = splat2(greg[i]);
    __syncthreads();

    const int NTILE = NN / KT;   // 256
    for (int kt = 0; kt < NTILE; ++kt) {
        const int cur = kt & 1;
        if (kt + 1 < NTILE) {
            const float* An = Ab + (size_t)(kt + 1) * KT;
            const float* Gn = Gb + (size_t)(kt + 1) * KT * DD;
            #pragma unroll
            for (int i = 0; i < 4; ++i)
                areg[i] = *(const float4*)(An + (size_t)(a_row + 32 * i) * NN + a_kc * 4);
            #pragma unroll
            for (int i = 0; i < 8; ++i)
                greg[i] = Gn[(size_t)(g_k0 + 2 * i) * DD + g_c];
        }

        #pragma unroll
        for (int k = 0; k < KT; ++k) {
            ulonglong2 a01 = *(const ulonglong2*)&As[cur][k][8 * ty];
            ulonglong2 a23 = *(const ulonglong2*)&As[cur][k][8 * ty + 4];
            #pragma unroll
            for (int q = 0; q < 4; ++q) {
                int j = (4 * tx + q) ^ (tx >> 1);   // swizzled 16B chunk
                ulonglong2 g = *(const ulonglong2*)&Gs[cur][k][j * 2];
                fma2(acc[0][2 * q + 0], a01.x, g.x);
                fma2(acc[0][2 * q + 1], a01.x, g.y);
                fma2(acc[1][2 * q + 0], a01.y, g.x);
                fma2(acc[1][2 * q + 1], a01.y, g.y);
                fma2(acc[2][2 * q + 0], a23.x, g.x);
                fma2(acc[2][2 * q + 1], a23.x, g.y);
                fma2(acc[3][2 * q + 0], a23.y, g.x);
                fma2(acc[3][2 * q + 1], a23.y, g.y);
            }
        }

        if (kt + 1 < NTILE) {
            const int nxt = cur ^ 1;
            #pragma unroll
            for (int i = 0; i < 4; ++i) {
                int r = a_row + 32 * i;
                As[nxt][4 * a_kc + 0][r] = areg[i].x;
                As[nxt][4 * a_kc + 1][r] = areg[i].y;
                As[nxt][4 * a_kc + 2][r] = areg[i].z;
                As[nxt][4 * a_kc + 3][r] = areg[i].w;
            }
            #pragma unroll
            for (int i = 0; i < 8; ++i)
                Gs[nxt][g_k0 + 2 * i][g_sidx] = splat2(greg[i]);
        }
        __syncthreads();
    }

    // ---- epilogue: out[r] = dinv_r * (acc_r + G_r) ----
    const float* dinvB = g_dinv + b * NN + row0;
    const float* Grow  = Gb + (size_t)row0 * DD;
    float*       outB  = out + ((size_t)b * NN + row0) * DD;

    #pragma unroll
    for (int rp = 0; rp < 4; ++rp) {
        float2 v[8];
        #pragma unroll
        for (int c = 0; c < 8; ++c) v[c] = unpack2(acc[rp][c]);
        #pragma unroll
        for (int h = 0; h < 2; ++h) {
            int   r  = 8 * ty + 2 * rp + h;
            float dv = dinvB[r];
            float4 g0 = *(const float4*)(Grow + (size_t)r * DD + 8 * tx);
            float4 g1 = *(const float4*)(Grow + (size_t)r * DD + 8 * tx + 4);
            float a0 = h ? v[0].y : v[0].x;
            float a1 = h ? v[1].y : v[1].x;
            float a2 = h ? v[2].y : v[2].x;
            float a3 = h ? v[3].y : v[3].x;
            float a4 = h ? v[4].y : v[4].x;
            float a5 = h ? v[5].y : v[5].x;
            float a6 = h ? v[6].y : v[6].x;
            float a7 = h ? v[7].y : v[7].x;
            float4 o0, o1;
            o0.x = dv * (a0 + g0.x);
            o0.y = dv * (a1 + g0.y);
            o0.z = dv * (a2 + g0.z);
            o0.w = dv * (a3 + g0.w);
            o1.x = dv * (a4 + g1.x);
            o1.y = dv * (a5 + g1.y);
            o1.z = dv * (a6 + g1.z);
            o1.w = dv * (a7 + g1.w);
            *(float4*)(outB + (size_t)r * DD + 8 * tx)     = o0;
            *(float4*)(outB + (size_t)r * DD + 8 * tx + 4) = o1;
        }
    }
}

// ---------------- launch ----------------
extern "C" void kernel_launch(void* const* d_in, const int* in_sizes, int n_in,
                              void* d_out, int out_size) {
    (void)in_sizes; (void)n_in; (void)out_size;
    const float* X    = (const float*)d_in[0];
    const float* A    = (const float*)d_in[1];
    const float* W    = (const float*)d_in[2];
    const float* bias = (const float*)d_in[3];
    float* out = (float*)d_out;

    k_prep<<<BATCH * NN / 8, 256>>>(X, A, W, bias);
    dim3 g2(NN / MT, BATCH);
    k_agg<<<g2, 128>>>(A, out);
}